// round 17
// baseline (speedup 1.0000x reference)
#include <cuda_runtime.h>
#include <math.h>

#define NB    8192
#define ND    512
#define NK    8
#define FULL  0xffffffffu

#define THREADS 256
#define WARPS   (THREADS / 32)
#define NBLK    (NB / WARPS)

// ---- prep kernel geometry: block 0 sorts (R12 config), 1..128 do norms ----
#define ST    1024
#define PGRID 129
#define NBKT  8192
#define SORT_SMEM (NB * 8 * 2 + NBKT * 4 * 2 + 64 * 4)   // 196864 B

__device__ double g_acc;
__device__ int    g_done = 0;
__device__ float  g_slab[NB];   // labels in sorted order
__device__ int    g_sidx[NB];   // original row per sorted position
__device__ float  g_norm[NB];   // sum(x^2) per original row

// -------- Prep kernel: block 0 = bucket sort; blocks 1..128 = norms --------
__global__ void __launch_bounds__(ST) nest_prep_kernel(
    const float* __restrict__ L, const float* __restrict__ S)
{
    const int tid  = threadIdx.x;
    const int lane = tid & 31;
    const int wid  = tid >> 5;

    if (blockIdx.x != 0) {
        // norm blocks: 64 rows each, 2 rows/warp
        const int rbase = (blockIdx.x - 1) * 64;
        const float4* Sf4 = (const float4*)S;
#pragma unroll
        for (int j = 0; j < 2; j++) {
            const int row = rbase + wid * 2 + j;
            float s = 0.0f;
#pragma unroll
            for (int t = 0; t < 4; t++) {
                float4 x = Sf4[(size_t)row * 128 + lane + t * 32];
                s += x.x * x.x + x.y * x.y + x.z * x.z + x.w * x.w;
            }
#pragma unroll
            for (int off = 16; off > 0; off >>= 1)
                s += __shfl_xor_sync(FULL, s, off);
            if (lane == 0) g_norm[row] = s;
        }
        return;
    }

    // ---------------- sort block (R12 verbatim) ----------------
    extern __shared__ char sm[];
    unsigned long long* sKey  = (unsigned long long*)sm;          // [NB]
    unsigned long long* sOut  = sKey + NB;                        // [NB]
    int*                sHist = (int*)(sOut + NB);                // [NBKT]
    int*                sCur  = sHist + NBKT;                     // [NBKT]
    int*                sWarp = sCur + NBKT;                      // [64]

    if (tid == 0) g_acc = 0.0;

    for (int i = tid; i < NBKT; i += ST) sHist[i] = 0;
    __syncthreads();

    for (int i = tid; i < NB; i += ST) {
        float v = L[i];
        sKey[i] = ((unsigned long long)__float_as_uint(v) << 13) | (unsigned)i;
        int b = (int)(v * (float)NBKT);
        b = max(0, min(b, NBKT - 1));
        atomicAdd(&sHist[b], 1);
    }
    __syncthreads();

    const int base = tid * 8;
    int local[8];
    int sum = 0;
#pragma unroll
    for (int j = 0; j < 8; j++) { local[j] = sum; sum += sHist[base + j]; }

    int v = sum;
#pragma unroll
    for (int off = 1; off < 32; off <<= 1) {
        int o = __shfl_up_sync(FULL, v, off);
        if (lane >= off) v += o;
    }
    if (lane == 31) sWarp[wid] = v;
    __syncthreads();
    if (wid == 0) {
        int wv = sWarp[lane];
#pragma unroll
        for (int off = 1; off < 32; off <<= 1) {
            int o = __shfl_up_sync(FULL, wv, off);
            if (lane >= off) wv += o;
        }
        sWarp[lane] = wv;
    }
    __syncthreads();
    const int warpBase = (wid > 0) ? sWarp[wid - 1] : 0;
    const int myExcl   = warpBase + v - sum;
#pragma unroll
    for (int j = 0; j < 8; j++) {
        int s = myExcl + local[j];
        sHist[base + j] = s;
        sCur[base + j]  = s;
    }
    __syncthreads();

    for (int i = tid; i < NB; i += ST) {
        unsigned long long k = sKey[i];
        float val = __uint_as_float((unsigned)(k >> 13));
        int b = max(0, min((int)(val * (float)NBKT), NBKT - 1));
        int pos = atomicAdd(&sCur[b], 1);
        sOut[pos] = k;
    }
    __syncthreads();

    for (int b = tid; b < NBKT; b += ST) {
        int st = sHist[b];
        int en = sCur[b];
        for (int i = st + 1; i < en; i++) {
            unsigned long long key = sOut[i];
            int j = i - 1;
            while (j >= st && sOut[j] > key) { sOut[j + 1] = sOut[j]; j--; }
            sOut[j + 1] = key;
        }
    }
    __syncthreads();

    for (int r = tid; r < NB; r += ST) {
        unsigned long long k = sOut[r];
        g_slab[r] = __uint_as_float((unsigned)(k >> 13));
        g_sidx[r] = (int)(k & 0x1FFFu);
    }
}

// ------------- Main kernel: branch-free contiguous-window select ------------
// d over the 15-candidate window is V-shaped (labels sorted), so the
// nearest-8 set is the contiguous window [a, a+7] minimizing its endpoint
// max. All label loads are independent (no dependent pointer chase).
__global__ void __launch_bounds__(THREADS) nest_main_kernel(
    const float* __restrict__ S, float* __restrict__ out)
{
    __shared__ double sSim[WARPS];

    const int tid  = threadIdx.x;
    const int wid  = tid >> 5;
    const int lane = tid & 31;

    const int r    = blockIdx.x * WARPS + wid;  // sorted position
    const int base = r - 7;

    // 15 independent L1 broadcast label loads
    float lab[15];
#pragma unroll
    for (int i = 0; i < 15; i++) {
        int p = base + i;
        lab[i] = (p >= 0 && p < NB) ? g_slab[p] : 1e30f;
    }
    const float Lb = lab[7];

    float dw[15];
#pragma unroll
    for (int i = 0; i < 15; i++) dw[i] = fabsf(lab[i] - Lb);

    // argmin over 8 candidate windows; max is at an endpoint (V-shape)
    float best = fmaxf(dw[0], dw[7]);
    int a = 0;
#pragma unroll
    for (int aa = 1; aa < 8; aa++) {
        float m = fmaxf(dw[aa], dw[aa + 7]);
        if (m < best) { best = m; a = aa; }
    }
    const int s0 = base + a;

    // 8 independent idx/label loads + weights
    int   gidx[NK];
    float w[NK];
    float wsum = 0.0f;
#pragma unroll
    for (int j = 0; j < NK; j++) {
        int p = s0 + j;
        gidx[j] = g_sidx[p];
        float dj = fabsf(g_slab[p] - Lb);
        float e  = __expf(-dj * dj * (1.0f / 50.0f));   // 2*STD^2 = 50
        w[j] = e; wsum += e;
    }
    const float winv = 1.0f / wsum;
#pragma unroll
    for (int j = 0; j < NK; j++) w[j] *= winv;

    const int b = g_sidx[r];                    // original self row

    // fused gather + weighted mean + cosine terms (nx precomputed in prep)
    const float4* xr = (const float4*)(S + (size_t)b * ND);
    float dot = 0.0f, nm = 0.0f;

#pragma unroll
    for (int t = 0; t < 4; t++) {
        int col = lane + t * 32;
        float4 x = xr[col];
        float mx = 0.0f, my = 0.0f, mz = 0.0f, mw = 0.0f;
#pragma unroll
        for (int k = 0; k < NK; k++) {
            float4 s = ((const float4*)(S + (size_t)gidx[k] * ND))[col];
            mx = fmaf(w[k], s.x, mx);
            my = fmaf(w[k], s.y, my);
            mz = fmaf(w[k], s.z, mz);
            mw = fmaf(w[k], s.w, mw);
        }
        dot += x.x * mx + x.y * my + x.z * mz + x.w * mw;
        nm  += mx * mx + my * my + mz * mz + mw * mw;
    }

#pragma unroll
    for (int off = 16; off > 0; off >>= 1) {
        dot += __shfl_xor_sync(FULL, dot, off);
        nm  += __shfl_xor_sync(FULL, nm,  off);
    }

    if (lane == 0) {
        float nx  = g_norm[b];
        float sim = dot / ((1e-10f + sqrtf(nx)) * (1e-10f + sqrtf(nm)));
        sSim[wid] = (double)sim;
    }
    __syncthreads();

    if (tid == 0) {
        double bs = 0.0;
#pragma unroll
        for (int k = 0; k < WARPS; k++) bs += sSim[k];
        atomicAdd(&g_acc, bs);
        __threadfence();
        int old = atomicAdd(&g_done, 1);
        if (old == NBLK - 1) {                  // last block finalizes
            double total = *((volatile double*)&g_acc);
            out[0] = (float)(1.0 - total / (double)NB);
            g_done = 0;                         // reset for graph replay
        }
    }
}

extern "C" void kernel_launch(void* const* d_in, const int* in_sizes, int n_in,
                              void* d_out, int out_size)
{
    const float* S = (const float*)d_in[0];   // Struct [8192, 512]
    const float* L = (const float*)d_in[1];   // Label  [8192]
    float* out = (float*)d_out;

    (void)cudaFuncSetAttribute(nest_prep_kernel,
                               cudaFuncAttributeMaxDynamicSharedMemorySize,
                               SORT_SMEM);

    nest_prep_kernel<<<PGRID, ST, SORT_SMEM>>>(L, S);
    nest_main_kernel<<<NBLK, THREADS>>>(S, out);
}